// round 2
// baseline (speedup 1.0000x reference)
#include <cuda_runtime.h>
#include <cuda_bf16.h>

// Problem constants
#define BB 64
#define SS 2048
#define HH 512
#define H4 128   // H in float4 units

// Scratch (module-scope device globals; no runtime allocation)
__device__ float4 g_P[SS * H4];    // pos_table @ W[0:512]     (4 MB)
__device__ float4 g_N[16 * H4];    // nest_table @ W[512:1024] (32 KB)
__device__ float4 g_G[8 * H4];     // seg_table @ W[1024:1536] (16 KB)
__device__ unsigned char g_combo[BB * SS];  // (nest<<3)|seg per token

// ---------------------------------------------------------------------------
// packed-fp32 helpers (sm_10x full-rate fp32 path; ptxas never emits FFMA2
// from plain C++)
// ---------------------------------------------------------------------------
__device__ __forceinline__ void fma2(unsigned long long& d,
                                     unsigned long long a,
                                     unsigned long long b) {
    asm("fma.rn.f32x2 %0, %1, %2, %0;" : "+l"(d) : "l"(a), "l"(b));
}
__device__ __forceinline__ unsigned long long dup2(float x) {
    unsigned long long r;
    asm("mov.b64 %0, {%1, %1};" : "=l"(r) : "f"(x));
    return r;
}

// ---------------------------------------------------------------------------
// Kernel 1: per-row syntax scan. 64 blocks x 128 threads.
// Lindley recursion via (delta-sum, min-prefix) segment aggregates.
// ---------------------------------------------------------------------------
__global__ void scan_kernel(const int* __restrict__ tok) {
    __shared__ int sh_tok[SS];
    __shared__ int agg_sum[128];
    __shared__ int agg_min[128];
    __shared__ int agg_cnt[128];

    const int b = blockIdx.x;
    const int* t = tok + b * SS;
    for (int i = threadIdx.x; i < SS; i += 128) sh_tok[i] = t[i];
    __syncthreads();

    const int j = threadIdx.x;
    const int base = j * 16;

    int s = 0, mn = 0, cnt = 0;
#pragma unroll
    for (int e = 0; e < 16; e++) {
        int tk = sh_tok[base + e];
        int op = (tk == 40) | (tk == 123) | (tk == 91);
        int cl = (tk == 41) | (tk == 125) | (tk == 93);
        s += op - cl;
        mn = min(mn, s);
        cnt += (tk > 39990);
    }
    agg_sum[j] = s; agg_min[j] = mn; agg_cnt[j] = cnt;
    __syncthreads();

    int S_pre = 0, M_pre = 0, C_pre = 0;
    for (int k = 0; k < j; k++) {
        M_pre = min(M_pre, S_pre + agg_min[k]);
        S_pre += agg_sum[k];
        C_pre += agg_cnt[k];
    }

    s = S_pre; mn = M_pre; cnt = C_pre;
    unsigned char* out = g_combo + b * SS + base;
#pragma unroll
    for (int e = 0; e < 16; e++) {
        int tk = sh_tok[base + e];
        int op = (tk == 40) | (tk == 123) | (tk == 91);
        int cl = (tk == 41) | (tk == 125) | (tk == 93);
        s += op - cl;
        mn = min(mn, s);
        cnt += (tk > 39990);
        int lvl = min(s - mn, 15);
        int seg = cnt & 7;
        out[e] = (unsigned char)((lvl << 3) | seg);
    }
}

// ---------------------------------------------------------------------------
// Kernel 2: big P GEMM.  C[2048,512] = pos_table[2048,512] @ W[0:512,512]
// BM=128, BN=64, BK=16, 128 threads, 8x8 microtile, packed fma.rn.f32x2.
// grid (16, 8) = 128 CTAs = one wave.
// ---------------------------------------------------------------------------
#define BM 128
#define BN 64
#define BK 16
#define APAD 4   // shift bank pattern per k-row for the transpose stores

__global__ void __launch_bounds__(128)
gemm_pos(const float* __restrict__ A, const float* __restrict__ B) {
    __shared__ float As[BK][BM + APAD];   // transposed: As[k][m]
    __shared__ float Bs[BK][BN];          // Bs[k][n]

    float* C = (float*)g_P;

    const int tid = threadIdx.x;
    const int tx = tid & 7;        // n: 8 groups of 8 cols
    const int ty = tid >> 3;       // m: 16 groups of 8 rows
    const int m0 = blockIdx.x * BM;
    const int n0 = blockIdx.y * BN;

    unsigned long long acc[8][4];
#pragma unroll
    for (int i = 0; i < 8; i++)
#pragma unroll
        for (int jj = 0; jj < 4; jj++) acc[i][jj] = 0ULL;

    for (int k0 = 0; k0 < 512; k0 += BK) {
        // A tile: 128 rows x 16 cols = 512 float4; 4 per thread, transposed in
#pragma unroll
        for (int l = 0; l < 4; l++) {
            int q = tid + l * 128;
            int r = q >> 2;        // row 0..127
            int c4 = q & 3;        // k-chunk 0..3
            float4 v = *(const float4*)(A + (size_t)(m0 + r) * 512 + k0 + c4 * 4);
            As[c4 * 4 + 0][r] = v.x;
            As[c4 * 4 + 1][r] = v.y;
            As[c4 * 4 + 2][r] = v.z;
            As[c4 * 4 + 3][r] = v.w;
        }
        // B tile: 16 rows x 64 cols = 256 float4; 2 per thread
#pragma unroll
        for (int l = 0; l < 2; l++) {
            int q = tid + l * 128;
            int kr = q >> 4;       // 0..15
            int c4 = q & 15;       // 0..15
            *(float4*)(&Bs[kr][c4 * 4]) =
                *(const float4*)(B + (size_t)(k0 + kr) * 512 + n0 + c4 * 4);
        }
        __syncthreads();

#pragma unroll
        for (int k = 0; k < BK; k++) {
            float4 a0 = *(float4*)(&As[k][ty * 8]);
            float4 a1 = *(float4*)(&As[k][ty * 8 + 4]);
            ulonglong2 b0 = *(ulonglong2*)(&Bs[k][tx * 8]);
            ulonglong2 b1 = *(ulonglong2*)(&Bs[k][tx * 8 + 4]);
            unsigned long long bp[4] = {b0.x, b0.y, b1.x, b1.y};
            unsigned long long ad[8];
            ad[0] = dup2(a0.x); ad[1] = dup2(a0.y);
            ad[2] = dup2(a0.z); ad[3] = dup2(a0.w);
            ad[4] = dup2(a1.x); ad[5] = dup2(a1.y);
            ad[6] = dup2(a1.z); ad[7] = dup2(a1.w);
#pragma unroll
            for (int i = 0; i < 8; i++)
#pragma unroll
                for (int jj = 0; jj < 4; jj++)
                    fma2(acc[i][jj], ad[i], bp[jj]);
        }
        __syncthreads();
    }

#pragma unroll
    for (int i = 0; i < 8; i++) {
        size_t m = m0 + ty * 8 + i;
        ulonglong2 o0, o1;
        o0.x = acc[i][0]; o0.y = acc[i][1];
        o1.x = acc[i][2]; o1.y = acc[i][3];
        *(ulonglong2*)(C + m * 512 + n0 + tx * 8) = o0;
        *(ulonglong2*)(C + m * 512 + n0 + tx * 8 + 4) = o1;
    }
}

// ---------------------------------------------------------------------------
// Kernel 3: small tables GEMM.  Rows 0..15 -> N = nest_table @ W[512:1024],
// rows 16..23 -> G = seg_table @ W[1024:1536].
// grid (24, 2): block = one output row x 256 cols. A-row cached in smem,
// W reads fully coalesced; everything L2-resident.
// ---------------------------------------------------------------------------
__global__ void __launch_bounds__(256)
gemm_small(const float* __restrict__ nest, const float* __restrict__ seg,
           const float* __restrict__ W) {
    __shared__ float arow[512];
    const int r = blockIdx.x;            // 0..23
    const bool is_nest = (r < 16);
    const float* a = is_nest ? (nest + r * 512) : (seg + (r - 16) * 512);
    const float* Wp = W + (is_nest ? 512 * 512 : 1024 * 512);
    float* out = is_nest ? (float*)g_N + r * 512 : (float*)g_G + (r - 16) * 512;

    const int tid = threadIdx.x;
    arow[tid] = a[tid];
    arow[tid + 256] = a[tid + 256];
    __syncthreads();

    const int col = blockIdx.y * 256 + tid;
    float acc = 0.f;
#pragma unroll 8
    for (int k = 0; k < 512; k++)
        acc += arow[k] * Wp[(size_t)k * 512 + col];
    out[col] = acc;
}

// ---------------------------------------------------------------------------
// Kernel 4: combine.  out[b,s,h] = P[s,h] + N[nest,h] + G[seg,h]
// One thread per (s,h4), loops over 8 batches -> P re-read from L2 8x not 64x.
// DRAM-write-bound (256 MB).
// ---------------------------------------------------------------------------
__global__ void __launch_bounds__(256)
combine_kernel(float4* __restrict__ out) {
    unsigned int j = blockIdx.x * 256u + threadIdx.x;
    const int h4 = j & 127;
    const int s = (j >> 7) & 2047;
    const int bo = j >> 18;              // 0..7

    const float4 p = g_P[s * H4 + h4];
#pragma unroll
    for (int bb = 0; bb < 8; bb++) {
        const int b = bo * 8 + bb;
        const unsigned char c = g_combo[b * SS + s];
        const float4 n = g_N[(c >> 3) * H4 + h4];
        const float4 g = g_G[(c & 7) * H4 + h4];
        float4 o;
        o.x = p.x + n.x + g.x;
        o.y = p.y + n.y + g.y;
        o.z = p.z + n.z + g.z;
        o.w = p.w + n.w + g.w;
        out[(((unsigned)b * SS + s) << 7) + h4] = o;
    }
}

// ---------------------------------------------------------------------------
extern "C" void kernel_launch(void* const* d_in, const int* in_sizes, int n_in,
                              void* d_out, int out_size) {
    const int*   tok  = (const int*)d_in[0];    // token_ids [64,2048] int32
    const float* pos  = (const float*)d_in[1];  // pos_table [2048,512]
    const float* nest = (const float*)d_in[2];  // nest_table [16,512]
    const float* seg  = (const float*)d_in[3];  // seg_table [8,512]
    const float* W    = (const float*)d_in[4];  // W [1536,512]
    float4* out = (float4*)d_out;               // [64,2048,512] f32

    scan_kernel<<<BB, 128>>>(tok);
    gemm_small<<<dim3(24, 2), 256>>>(nest, seg, W);
    gemm_pos<<<dim3(SS / BM, 512 / BN), 128>>>(pos, W);
    combine_kernel<<<(BB * SS * H4 / 8) / 256, 256>>>(out);
}